// round 3
// baseline (speedup 1.0000x reference)
#include <cuda_runtime.h>
#include <cstdint>

// ---------------------------------------------------------------------------
// Problem constants
// ---------------------------------------------------------------------------
#define EN   768
#define SS   64
#define BBATCH 1024
#define HH   12
#define HIDN 3072
#define M_ROWS (BBATCH * SS)   // 65536

// ---------------------------------------------------------------------------
// Scratch (allocation-free rule: __device__ globals)
// ---------------------------------------------------------------------------
__device__ float g_hn[(size_t)M_ROWS * EN];   // LN output (reused for both LNs)
__device__ float g_q [(size_t)M_ROWS * EN];
__device__ float g_k [(size_t)M_ROWS * EN];
__device__ float g_v [(size_t)M_ROWS * EN];
__device__ float g_h [(size_t)M_ROWS * HIDN]; // gelu(hn2 @ W1 + b1)

// ---------------------------------------------------------------------------
// Helpers
// ---------------------------------------------------------------------------
__device__ __forceinline__ float to_tf32(float x) {
    unsigned int u;
    asm("cvt.rna.tf32.f32 %0, %1;" : "=r"(u) : "f"(x));
    return __uint_as_float(u);
}

__device__ __forceinline__ void mma8(float* d, const unsigned int* a, const unsigned int* b) {
    asm volatile(
        "mma.sync.aligned.m16n8k8.row.col.f32.tf32.tf32.f32 "
        "{%0,%1,%2,%3}, {%4,%5,%6,%7}, {%8,%9}, {%0,%1,%2,%3};"
        : "+f"(d[0]), "+f"(d[1]), "+f"(d[2]), "+f"(d[3])
        : "r"(a[0]), "r"(a[1]), "r"(a[2]), "r"(a[3]),
          "r"(b[0]), "r"(b[1]));
}

__device__ __forceinline__ float gelu_exact(float x) {
    return 0.5f * x * (1.0f + erff(x * 0.70710678118654752f));
}

// ---------------------------------------------------------------------------
// LayerNorm: one block (256 threads) per row of 768
// ---------------------------------------------------------------------------
__global__ __launch_bounds__(256)
void ln_kernel(const float* __restrict__ x, const float* __restrict__ gw,
               const float* __restrict__ bw, float* __restrict__ y)
{
    const int row = blockIdx.x;
    const float* xr = x + (size_t)row * EN;
    float* yr = y + (size_t)row * EN;
    const int tid = threadIdx.x;

    float v0 = xr[tid];
    float v1 = xr[tid + 256];
    float v2 = xr[tid + 512];
    float s1 = v0 + v1 + v2;
    float s2 = v0 * v0 + v1 * v1 + v2 * v2;

    __shared__ float red[16];
    #pragma unroll
    for (int o = 16; o > 0; o >>= 1) {
        s1 += __shfl_xor_sync(0xffffffffu, s1, o);
        s2 += __shfl_xor_sync(0xffffffffu, s2, o);
    }
    const int warp = tid >> 5, lane = tid & 31;
    if (lane == 0) { red[warp] = s1; red[8 + warp] = s2; }
    __syncthreads();
    float t1 = 0.f, t2 = 0.f;
    #pragma unroll
    for (int i = 0; i < 8; i++) { t1 += red[i]; t2 += red[8 + i]; }

    const float mu   = t1 * (1.0f / EN);
    const float var  = t2 * (1.0f / EN) - mu * mu;
    const float rstd = rsqrtf(var + 1e-6f);

    yr[tid]       = (v0 - mu) * rstd * gw[tid]       + bw[tid];
    yr[tid + 256] = (v1 - mu) * rstd * gw[tid + 256] + bw[tid + 256];
    yr[tid + 512] = (v2 - mu) * rstd * gw[tid + 512] + bw[tid + 512];
}

// ---------------------------------------------------------------------------
// tf32 tensor-core GEMM:  C[M,N] = A[M,K] @ B[K,N] + bias  (+ epilogue)
//   EPI 0: bias                          (QKV projections)
//   EPI 1: gelu(acc + bias)              (MLP fc1)
//   EPI 2: acc + bias + C[in-place]      (MLP fc2 + residual)
// 128x128x16 CTA tile, 8 warps as 2x4, warp tile 64x32 (4x4 m16n8k8 frags),
// register-staged double buffer. M,N,K all multiples of the tiles -> no guards.
// ---------------------------------------------------------------------------
#define BM 128
#define BN 128
#define BK 16
#define AST 20    // A smem row stride (conflict-free: 20%32=20 spreads 8 rows x 4 cols over 32 banks)
#define BST 136   // B smem row stride (136%32=8 spreads 4 rows x 8 cols over 32 banks)

template <int EPI>
__global__ __launch_bounds__(256)
void gemm_tf32(const float* __restrict__ A, const float* __restrict__ B,
               const float* __restrict__ bias, float* __restrict__ C,
               int M, int N, int K)
{
    __shared__ __align__(16) float As[2][BM][AST];
    __shared__ __align__(16) float Bs[2][BK][BST];

    const int tid  = threadIdx.x;
    const int lane = tid & 31;
    const int warp = tid >> 5;
    const int rowBase = (warp >> 2) * 64;   // 0 or 64
    const int colBase = (warp & 3) * 32;    // 0,32,64,96
    const int lrow = lane >> 2;             // 0..7
    const int lcol = lane & 3;              // 0..3

    const int bM = blockIdx.y * BM;
    const int bN = blockIdx.x * BN;

    // global-load mapping: A tile 128x16 -> 2 float4/thread; B tile 16x128 -> 2 float4/thread
    const int ar0 = tid >> 2;          // A rows ar0, ar0+64
    const int ac  = (tid & 3) * 4;     // A col within tile
    const int br0 = tid >> 5;          // B rows br0, br0+8
    const int bc  = lane * 4;          // B col within tile

    const float* Ag = A + (size_t)(bM + ar0) * K + ac;
    const float* Bg = B + bN + bc;

    float4 sa0, sa1, sb0, sb1;
    float acc[4][4][4];
    #pragma unroll
    for (int i = 0; i < 4; i++)
        #pragma unroll
        for (int j = 0; j < 4; j++)
            #pragma unroll
            for (int q = 0; q < 4; q++) acc[i][j][q] = 0.f;

    const int KT = K / BK;

    // prologue: tile 0 -> regs -> (cvt) -> smem buf 0
    {
        sa0 = *reinterpret_cast<const float4*>(Ag);
        sa1 = *reinterpret_cast<const float4*>(Ag + (size_t)64 * K);
        sb0 = *reinterpret_cast<const float4*>(Bg + (size_t)br0 * N);
        sb1 = *reinterpret_cast<const float4*>(Bg + (size_t)(br0 + 8) * N);
        float4 w;
        w.x = to_tf32(sa0.x); w.y = to_tf32(sa0.y); w.z = to_tf32(sa0.z); w.w = to_tf32(sa0.w);
        *reinterpret_cast<float4*>(&As[0][ar0][ac]) = w;
        w.x = to_tf32(sa1.x); w.y = to_tf32(sa1.y); w.z = to_tf32(sa1.z); w.w = to_tf32(sa1.w);
        *reinterpret_cast<float4*>(&As[0][ar0 + 64][ac]) = w;
        w.x = to_tf32(sb0.x); w.y = to_tf32(sb0.y); w.z = to_tf32(sb0.z); w.w = to_tf32(sb0.w);
        *reinterpret_cast<float4*>(&Bs[0][br0][bc]) = w;
        w.x = to_tf32(sb1.x); w.y = to_tf32(sb1.y); w.z = to_tf32(sb1.z); w.w = to_tf32(sb1.w);
        *reinterpret_cast<float4*>(&Bs[0][br0 + 8][bc]) = w;
    }
    __syncthreads();

    for (int kt = 0; kt < KT; ++kt) {
        const int buf = kt & 1;

        // prefetch next tile into registers (latency hidden behind the mma block)
        if (kt + 1 < KT) {
            const int ko = (kt + 1) * BK;
            sa0 = *reinterpret_cast<const float4*>(Ag + ko);
            sa1 = *reinterpret_cast<const float4*>(Ag + (size_t)64 * K + ko);
            sb0 = *reinterpret_cast<const float4*>(Bg + (size_t)(ko + br0) * N);
            sb1 = *reinterpret_cast<const float4*>(Bg + (size_t)(ko + br0 + 8) * N);
        }

        // compute on current buffer: 2 k-steps of 8, 4x4 fragment grid
        #pragma unroll
        for (int ks = 0; ks < 2; ++ks) {
            const int k0 = ks * 8;
            unsigned int af[4][4], bf[4][2];
            #pragma unroll
            for (int mf = 0; mf < 4; ++mf) {
                const int r = rowBase + mf * 16 + lrow;
                af[mf][0] = __float_as_uint(As[buf][r    ][k0 + lcol    ]);
                af[mf][1] = __float_as_uint(As[buf][r + 8][k0 + lcol    ]);
                af[mf][2] = __float_as_uint(As[buf][r    ][k0 + lcol + 4]);
                af[mf][3] = __float_as_uint(As[buf][r + 8][k0 + lcol + 4]);
            }
            #pragma unroll
            for (int nf = 0; nf < 4; ++nf) {
                const int c = colBase + nf * 8 + lrow;
                bf[nf][0] = __float_as_uint(Bs[buf][k0 + lcol    ][c]);
                bf[nf][1] = __float_as_uint(Bs[buf][k0 + lcol + 4][c]);
            }
            #pragma unroll
            for (int mf = 0; mf < 4; ++mf)
                #pragma unroll
                for (int nf = 0; nf < 4; ++nf)
                    mma8(acc[mf][nf], af[mf], bf[nf]);
        }

        // stage next tile into the other buffer
        if (kt + 1 < KT) {
            const int nb = buf ^ 1;
            float4 w;
            w.x = to_tf32(sa0.x); w.y = to_tf32(sa0.y); w.z = to_tf32(sa0.z); w.w = to_tf32(sa0.w);
            *reinterpret_cast<float4*>(&As[nb][ar0][ac]) = w;
            w.x = to_tf32(sa1.x); w.y = to_tf32(sa1.y); w.z = to_tf32(sa1.z); w.w = to_tf32(sa1.w);
            *reinterpret_cast<float4*>(&As[nb][ar0 + 64][ac]) = w;
            w.x = to_tf32(sb0.x); w.y = to_tf32(sb0.y); w.z = to_tf32(sb0.z); w.w = to_tf32(sb0.w);
            *reinterpret_cast<float4*>(&Bs[nb][br0][bc]) = w;
            w.x = to_tf32(sb1.x); w.y = to_tf32(sb1.y); w.z = to_tf32(sb1.z); w.w = to_tf32(sb1.w);
            *reinterpret_cast<float4*>(&Bs[nb][br0 + 8][bc]) = w;
        }
        __syncthreads();
    }

    // epilogue
    #pragma unroll
    for (int mf = 0; mf < 4; ++mf) {
        const int r = bM + rowBase + mf * 16 + lrow;
        #pragma unroll
        for (int nf = 0; nf < 4; ++nf) {
            const int c = bN + colBase + nf * 8 + lcol * 2;
            const float b0 = bias[c], b1 = bias[c + 1];
            float v00 = acc[mf][nf][0] + b0;
            float v01 = acc[mf][nf][1] + b1;
            float v10 = acc[mf][nf][2] + b0;
            float v11 = acc[mf][nf][3] + b1;
            const size_t i0 = (size_t)r * N + c;
            const size_t i1 = (size_t)(r + 8) * N + c;
            if (EPI == 1) {
                v00 = gelu_exact(v00); v01 = gelu_exact(v01);
                v10 = gelu_exact(v10); v11 = gelu_exact(v11);
            } else if (EPI == 2) {
                const float2 r0 = *reinterpret_cast<const float2*>(&C[i0]);
                const float2 r1 = *reinterpret_cast<const float2*>(&C[i1]);
                v00 += r0.x; v01 += r0.y; v10 += r1.x; v11 += r1.y;
            }
            *reinterpret_cast<float2*>(&C[i0]) = make_float2(v00, v01);
            *reinterpret_cast<float2*>(&C[i1]) = make_float2(v10, v11);
        }
    }
}

// ---------------------------------------------------------------------------
// Fused attention per (b, h): score = softmax(q k^T / sqrt(E)),
// attn = v @ score, out = image + attn (reshape [B,H,S,S]->[B,S,E] is the
// identity on the flat index:  out[b*49152 + h*4096 + s*64 + t]).
// 256 threads; each owns a 4x4 (s,t) micro-tile.
// ---------------------------------------------------------------------------
__global__ __launch_bounds__(256)
void attn_kernel(const float* __restrict__ Q, const float* __restrict__ K,
                 const float* __restrict__ V, const float* __restrict__ img,
                 float* __restrict__ out)
{
    __shared__ float bufA[64][65];   // q, then score^T (scT[t][d])
    __shared__ float bufB[64][65];   // k, then v
    __shared__ float red[64][17];
    __shared__ float rowmax[64];
    __shared__ float rowinv[64];

    const int bh = blockIdx.x;
    const int b  = bh / HH;
    const int h  = bh - b * HH;
    const size_t goff = (size_t)b * SS * EN + (size_t)h * SS;  // 64x64 tile, row stride EN

    const int tid = threadIdx.x;

    // load q, k tiles (4096 floats each; 4 x float4 per thread, scalar smem stores)
    #pragma unroll
    for (int i = 0; i < 4; i++) {
        const int id = tid + i * 256;
        const int r = id >> 4;
        const int c = (id & 15) * 4;
        const float4 qv = *reinterpret_cast<const float4*>(Q + goff + (size_t)r * EN + c);
        bufA[r][c] = qv.x; bufA[r][c + 1] = qv.y; bufA[r][c + 2] = qv.z; bufA[r][c + 3] = qv.w;
        const float4 kv = *reinterpret_cast<const float4*>(K + goff + (size_t)r * EN + c);
        bufB[r][c] = kv.x; bufB[r][c + 1] = kv.y; bufB[r][c + 2] = kv.z; bufB[r][c + 3] = kv.w;
    }
    __syncthreads();

    const int sg   = (tid & 15) * 4;   // s0
    const int tg   = (tid >> 4) * 4;   // t0
    const int tcol = tid >> 4;         // 0..15

    // score[s][t] = sum_d q[s][d] * k[t][d]
    float sc[4][4];
    #pragma unroll
    for (int i = 0; i < 4; i++)
        #pragma unroll
        for (int j = 0; j < 4; j++) sc[i][j] = 0.f;

    #pragma unroll 8
    for (int d = 0; d < 64; ++d) {
        float qv[4], kv[4];
        #pragma unroll
        for (int i = 0; i < 4; i++) qv[i] = bufA[sg + i][d];
        #pragma unroll
        for (int j = 0; j < 4; j++) kv[j] = bufB[tg + j][d];
        #pragma unroll
        for (int i = 0; i < 4; i++)
            #pragma unroll
            for (int j = 0; j < 4; j++) sc[i][j] += qv[i] * kv[j];
    }
    const float scale = 0.036084391824351615f;  // 1/sqrt(768)
    #pragma unroll
    for (int i = 0; i < 4; i++)
        #pragma unroll
        for (int j = 0; j < 4; j++) sc[i][j] *= scale;

    // rowwise max (over t)
    #pragma unroll
    for (int i = 0; i < 4; i++)
        red[sg + i][tcol] = fmaxf(fmaxf(sc[i][0], sc[i][1]), fmaxf(sc[i][2], sc[i][3]));
    __syncthreads();   // q/k reads all complete here

    if (tid < 64) {
        float m = red[tid][0];
        #pragma unroll
        for (int j = 1; j < 16; j++) m = fmaxf(m, red[tid][j]);
        rowmax[tid] = m;
    }
    // overlap: load v into bufB (k no longer needed)
    #pragma unroll
    for (int i = 0; i < 4; i++) {
        const int id = tid + i * 256;
        const int r = id >> 4;
        const int c = (id & 15) * 4;
        const float4 vv = *reinterpret_cast<const float4*>(V + goff + (size_t)r * EN + c);
        bufB[r][c] = vv.x; bufB[r][c + 1] = vv.y; bufB[r][c + 2] = vv.z; bufB[r][c + 3] = vv.w;
    }
    __syncthreads();

    // exp + rowwise sum
    float ls[4];
    #pragma unroll
    for (int i = 0; i < 4; i++) {
        const float rm = rowmax[sg + i];
        float s = 0.f;
        #pragma unroll
        for (int j = 0; j < 4; j++) { sc[i][j] = __expf(sc[i][j] - rm); s += sc[i][j]; }
        ls[i] = s;
    }
    #pragma unroll
    for (int i = 0; i < 4; i++) red[sg + i][tcol] = ls[i];
    __syncthreads();
    if (tid < 64) {
        float s = 0.f;
        #pragma unroll
        for (int j = 0; j < 16; j++) s += red[tid][j];
        rowinv[tid] = 1.0f / s;
    }
    __syncthreads();

    // write normalized score^T into bufA (q no longer needed): scT[t][s]
    #pragma unroll
    for (int i = 0; i < 4; i++) {
        const float inv = rowinv[sg + i];
        #pragma unroll
        for (int j = 0; j < 4; j++) bufA[tg + j][sg + i] = sc[i][j] * inv;
    }
    __syncthreads();

    // attn[s][t] = sum_d v[s][d] * scT[t][d]
    float at[4][4];
    #pragma unroll
    for (int i = 0; i < 4; i++)
        #pragma unroll
        for (int j = 0; j < 4; j++) at[i][j] = 0.f;

    #pragma unroll 8
    for (int d = 0; d < 64; ++d) {
        float vv[4], pv[4];
        #pragma unroll
        for (int i = 0; i < 4; i++) vv[i] = bufB[sg + i][d];
        #pragma unroll
        for (int j = 0; j < 4; j++) pv[j] = bufA[tg + j][d];
        #pragma unroll
        for (int i = 0; i < 4; i++)
            #pragma unroll
            for (int j = 0; j < 4; j++) at[i][j] += vv[i] * pv[j];
    }

    // out = image + attn at the flat-reshape offset
    const size_t obase = (size_t)b * (SS * EN) + (size_t)h * (SS * SS);
    #pragma unroll
    for (int i = 0; i < 4; i++) {
        const size_t idx = obase + (size_t)(sg + i) * SS + tg;
        const float4 im = *reinterpret_cast<const float4*>(img + idx);
        float4 o;
        o.x = im.x + at[i][0];
        o.y = im.y + at[i][1];
        o.z = im.z + at[i][2];
        o.w = im.w + at[i][3];
        *reinterpret_cast<float4*>(out + idx) = o;
    }
}

// ---------------------------------------------------------------------------
// Launch
// ---------------------------------------------------------------------------
extern "C" void kernel_launch(void* const* d_in, const int* in_sizes, int n_in,
                              void* d_out, int out_size)
{
    (void)in_sizes; (void)n_in; (void)out_size;
    const float* image = (const float*)d_in[0];
    const float* ln_g  = (const float*)d_in[1];
    const float* ln_b  = (const float*)d_in[2];
    const float* Wq = (const float*)d_in[3];
    const float* bq = (const float*)d_in[4];
    const float* Wk = (const float*)d_in[5];
    const float* bk = (const float*)d_in[6];
    const float* Wv = (const float*)d_in[7];
    const float* bv = (const float*)d_in[8];
    const float* W1 = (const float*)d_in[9];
    const float* b1 = (const float*)d_in[10];
    const float* W2 = (const float*)d_in[11];
    const float* b2 = (const float*)d_in[12];
    float* out = (float*)d_out;

    float *hn, *q, *k, *v, *hbuf;
    cudaGetSymbolAddress((void**)&hn,   g_hn);
    cudaGetSymbolAddress((void**)&q,    g_q);
    cudaGetSymbolAddress((void**)&k,    g_k);
    cudaGetSymbolAddress((void**)&v,    g_v);
    cudaGetSymbolAddress((void**)&hbuf, g_h);

    // 1) shared pre-norm
    ln_kernel<<<M_ROWS, 256>>>(image, ln_g, ln_b, hn);

    // 2) Q/K/V projections
    const dim3 gq(EN / BN, M_ROWS / BM);
    gemm_tf32<0><<<gq, 256>>>(hn, Wq, bq, q, M_ROWS, EN, EN);
    gemm_tf32<0><<<gq, 256>>>(hn, Wk, bk, k, M_ROWS, EN, EN);
    gemm_tf32<0><<<gq, 256>>>(hn, Wv, bv, v, M_ROWS, EN, EN);

    // 3) fused attention + residual -> d_out holds x
    attn_kernel<<<BBATCH * HH, 256>>>(q, k, v, image, out);

    // 4) second shared LN on x
    ln_kernel<<<M_ROWS, 256>>>(out, ln_g, ln_b, hn);

    // 5) MLP fc1 + exact gelu
    const dim3 g1(HIDN / BN, M_ROWS / BM);
    gemm_tf32<1><<<g1, 256>>>(hn, W1, b1, hbuf, M_ROWS, HIDN, EN);

    // 6) MLP fc2 + bias + residual (in place on d_out)
    gemm_tf32<2><<<gq, 256>>>(hbuf, W2, b2, out, M_ROWS, EN, HIDN);
}